// round 9
// baseline (speedup 1.0000x reference)
#include <cuda_runtime.h>

// VanillaRNN fused persistent kernel, v7.
// B=1024, T=512, I=64, H=128, O=10.
// Grid: 256 CTAs x 4 rows, 2 CTAs/SM (v5 topology -- v6's 296-CTA placement
// gamble reverted). NEW: software-pipelined x-part. z_t = Wx x_t + Wh h_{t-1};
// the Wx x_t partials for step t+1 (xa/xb, pre-reduced by one xor4 stage ->
// 8 carried floats) are computed in step t's independent tail, so the
// barrier-to-barrier dependent chain is only the h-part (128k) + tree.
//
// Thread mapping: g = warp*4 + (lane&3): col group, cols {g,g+32,g+64,g+96};
// seg = lane>>2 in [0,8). Seg owns h-k [16s,16s+16) and x-k [8s,8s+8).
// Tree: xor4 (row pairs), xor8 (rows->1), xor16 (cols 4->2).
// smem: h double buffer hb[2][4][160] (seg stride 20 floats: bases hit 8
// distinct 16B regions mod 128B, 16B-aligned); x double buffer xs[2][4][96]
// (seg stride 12). One barrier per step.

#define ROWS 4
#define NTHREADS 256
#define HDIM 128
#define IDIM 64
#define TSTEPS 512
#define ODIM 10
#define HSEGF 16
#define HSEGP 20
#define HROW 160       // 8*20
#define XSEGF 8
#define XSEGP 12
#define XROW 96        // 8*12
#define GRID 256

__device__ __forceinline__ unsigned long long ffma2(unsigned long long a,
                                                    unsigned long long b,
                                                    unsigned long long c) {
    unsigned long long d;
    asm("fma.rn.f32x2 %0, %1, %2, %3;" : "=l"(d) : "l"(a), "l"(b), "l"(c));
    return d;
}

__device__ __forceinline__ unsigned long long packf2(float lo, float hi) {
    return ((unsigned long long)__float_as_uint(hi) << 32) |
           (unsigned long long)__float_as_uint(lo);
}

__device__ __forceinline__ float sum2(unsigned long long a) {
    return __uint_as_float((unsigned)a) + __uint_as_float((unsigned)(a >> 32));
}

__device__ __forceinline__ float fast_tanh(float z) {
    float e = __expf(2.0f * z);
    return 1.0f - __fdividef(2.0f, e + 1.0f);
}

__device__ __forceinline__ int physh(int k) {          // k in [0,128)
    return (k / HSEGF) * HSEGP + (k % HSEGF);
}

// h-part: one row, this thread's 16 h-k, 4 cols -> sv[4]
__device__ __forceinline__ void row_acc_h(const float* __restrict__ rowbase,
                                          int segoff,
                                          const unsigned long long wh[4][8],
                                          float sv[4]) {
    const ulonglong2* pp = (const ulonglong2*)(rowbase + segoff);
    unsigned long long a0 = 0ull, a1 = 0ull, a2 = 0ull, a3 = 0ull;
#pragma unroll
    for (int i = 0; i < 4; i++) {
        ulonglong2 v = pp[i];
        a0 = ffma2(v.x, wh[0][2 * i], a0);
        a1 = ffma2(v.x, wh[1][2 * i], a1);
        a2 = ffma2(v.x, wh[2][2 * i], a2);
        a3 = ffma2(v.x, wh[3][2 * i], a3);
        a0 = ffma2(v.y, wh[0][2 * i + 1], a0);
        a1 = ffma2(v.y, wh[1][2 * i + 1], a1);
        a2 = ffma2(v.y, wh[2][2 * i + 1], a2);
        a3 = ffma2(v.y, wh[3][2 * i + 1], a3);
    }
    sv[0] = sum2(a0); sv[1] = sum2(a1); sv[2] = sum2(a2); sv[3] = sum2(a3);
}

// x-part: one row, this thread's 8 x-k, 4 cols -> sv[4]
__device__ __forceinline__ void row_acc_x(const float* __restrict__ rowbase,
                                          int segoff,
                                          const unsigned long long wx[4][4],
                                          float sv[4]) {
    const ulonglong2* pp = (const ulonglong2*)(rowbase + segoff);
    unsigned long long a0 = 0ull, a1 = 0ull, a2 = 0ull, a3 = 0ull;
#pragma unroll
    for (int i = 0; i < 2; i++) {
        ulonglong2 v = pp[i];
        a0 = ffma2(v.x, wx[0][2 * i], a0);
        a1 = ffma2(v.x, wx[1][2 * i], a1);
        a2 = ffma2(v.x, wx[2][2 * i], a2);
        a3 = ffma2(v.x, wx[3][2 * i], a3);
        a0 = ffma2(v.y, wx[0][2 * i + 1], a0);
        a1 = ffma2(v.y, wx[1][2 * i + 1], a1);
        a2 = ffma2(v.y, wx[2][2 * i + 1], a2);
        a3 = ffma2(v.y, wx[3][2 * i + 1], a3);
    }
    sv[0] = sum2(a0); sv[1] = sum2(a1); sv[2] = sum2(a2); sv[3] = sum2(a3);
}

__global__ void __launch_bounds__(NTHREADS, 2)
rnn_fused_kernel(const float* __restrict__ x,
                 const float* __restrict__ W_hx,
                 const float* __restrict__ W_hh,
                 const float* __restrict__ b_hh,
                 const float* __restrict__ W_ph,
                 const float* __restrict__ b_ph,
                 float* __restrict__ out) {
    __shared__ __align__(16) float hb[2][ROWS][HROW];
    __shared__ __align__(16) float xs[2][ROWS][XROW];

    const int tid  = threadIdx.x;
    const int lane = tid & 31;
    const int warp = tid >> 5;
    const int g    = warp * 4 + (lane & 3);   // col group 0..31
    const int seg  = lane >> 2;               // 0..7
    const int b0r  = blockIdx.x * ROWS;

    // ---- weights: h-part 4x8, x-part 4x4 packed f32x2 (96 regs total)
    unsigned long long wh[4][8], wx[4][4];
#pragma unroll
    for (int c = 0; c < 4; c++) {
        const int o = g + 32 * c;
#pragma unroll
        for (int j = 0; j < 8; j++) {
            const int k0 = seg * HSEGF + 2 * j;
            wh[c][j] = packf2(W_hh[o * HDIM + k0], W_hh[o * HDIM + k0 + 1]);
        }
#pragma unroll
        for (int j = 0; j < 4; j++) {
            const int k0 = seg * XSEGF + 2 * j;
            wx[c][j] = packf2(W_hx[o * IDIM + k0], W_hx[o * IDIM + k0 + 1]);
        }
    }

    const int sb0 = seg & 1, sb1 = (seg >> 1) & 1, sb2 = (seg >> 2) & 1;
    const bool low0 = (sb0 == 0);
    const int mstar = 2 * sb0 + sb1;
    const int of0 = g + 64 * sb2;
    const int of1 = of0 + 32;
    const float bb0 = b_hh[of0];
    const float bb1 = b_hh[of1];
    const int ph0 = physh(of0);
    const int ph1 = physh(of1);
    const int hsegoff = seg * HSEGP;
    const int xsegoff = seg * XSEGP;

    // ---- zero h buffers (h0 = 0)
    for (int i = tid; i < 2 * ROWS * HROW; i += NTHREADS)
        ((float*)hb)[i] = 0.0f;

    // ---- x loader: tid<64: row xr, float4 chunk c4 in [0,64)
    const int xr  = (tid >> 4) & 3;
    const int c4  = (tid & 15) * 4;
    const int px4 = (c4 / XSEGF) * XSEGP + (c4 % XSEGF);  // {0,4} within seg: ok
    const bool loader = (tid < 64);
    const float* xrow = x + (size_t)(b0r + xr) * TSTEPS * IDIM;

    if (loader) {
        *(float4*)&xs[0][xr][px4] = *(const float4*)(xrow + 0 * IDIM + c4);  // x_0
        *(float4*)&xs[1][xr][px4] = *(const float4*)(xrow + 1 * IDIM + c4);  // x_1
    }
    __syncthreads();

    // ---- pre-loop: x-partials for step 0 from xs[0] (x_0)
    float xa[4], xb[4];
    {
        float q0[4], q2[4], q1[4], q3[4];
        row_acc_x(&xs[0][0][0], xsegoff, wx, q0);
        row_acc_x(&xs[0][2][0], xsegoff, wx, q2);
        row_acc_x(&xs[0][1][0], xsegoff, wx, q1);
        row_acc_x(&xs[0][3][0], xsegoff, wx, q3);
#pragma unroll
        for (int c = 0; c < 4; c++) {
            float sendA = low0 ? q2[c] : q0[c];
            float recvA = __shfl_xor_sync(0xffffffffu, sendA, 4);
            xa[c] = (low0 ? q0[c] : q2[c]) + recvA;
            float sendB = low0 ? q3[c] : q1[c];
            float recvB = __shfl_xor_sync(0xffffffffu, sendB, 4);
            xb[c] = (low0 ? q1[c] : q3[c]) + recvB;
        }
    }
    __syncthreads();   // protect xs[0] from being overwritten in I_0

    int p = 0;
    for (int t = 0; t < TSTEPS; t++) {
        // LDG x_{t+2} (clamped) into regs, STS'd at end of this interval
        float4 xn;
        if (loader) {
            const int tn = (t + 2 < TSTEPS) ? t + 2 : TSTEPS - 1;
            xn = *(const float4*)(xrow + (size_t)tn * IDIM + c4);
        }

        const float* hbase = &hb[p][0][0];

        // ---- h-part pair A: rows {0,2}; stage-0 xor4; add pipelined x-part
        float ra[4];
        {
            float sA[4], sB[4];
            row_acc_h(hbase + 0 * HROW, hsegoff, wh, sA);
            row_acc_h(hbase + 2 * HROW, hsegoff, wh, sB);
#pragma unroll
            for (int c = 0; c < 4; c++) {
                float send = low0 ? sB[c] : sA[c];
                float recv = __shfl_xor_sync(0xffffffffu, send, 4);
                ra[c] = (low0 ? sA[c] : sB[c]) + recv + xa[c];
            }
        }
        // ---- h-part pair B: rows {1,3}
        float rb[4];
        {
            float sA[4], sB[4];
            row_acc_h(hbase + 1 * HROW, hsegoff, wh, sA);
            row_acc_h(hbase + 3 * HROW, hsegoff, wh, sB);
#pragma unroll
            for (int c = 0; c < 4; c++) {
                float send = low0 ? sB[c] : sA[c];
                float recv = __shfl_xor_sync(0xffffffffu, send, 4);
                rb[c] = (low0 ? sA[c] : sB[c]) + recv + xb[c];
            }
        }

        // ---- stage 1 (xor 8): rows 2 -> 1
        float rc[4];
        {
            const bool low = (sb1 == 0);
#pragma unroll
            for (int c = 0; c < 4; c++) {
                float send = low ? rb[c] : ra[c];
                float recv = __shfl_xor_sync(0xffffffffu, send, 8);
                rc[c] = (low ? ra[c] : rb[c]) + recv;
            }
        }
        // ---- stage 2 (xor 16): cols 4 -> 2
        float f0, f1;
        {
            const bool low = (sb2 == 0);
            float send0 = low ? rc[2] : rc[0];
            float send1 = low ? rc[3] : rc[1];
            float recv0 = __shfl_xor_sync(0xffffffffu, send0, 16);
            float recv1 = __shfl_xor_sync(0xffffffffu, send1, 16);
            f0 = (low ? rc[0] : rc[2]) + recv0;
            f1 = (low ? rc[1] : rc[3]) + recv1;
        }

        // ---- publish h_t
        const int q = p ^ 1;
        hb[q][mstar][ph0] = fast_tanh(f0 + bb0);
        hb[q][mstar][ph1] = fast_tanh(f1 + bb1);

        // ---- independent tail: x-partials for step t+1 from xs[(t+1)&1]
        {
            const float* xbase = &xs[(t + 1) & 1][0][0];
            float q0[4], q2[4], q1[4], q3[4];
            row_acc_x(xbase + 0 * XROW, xsegoff, wx, q0);
            row_acc_x(xbase + 2 * XROW, xsegoff, wx, q2);
            row_acc_x(xbase + 1 * XROW, xsegoff, wx, q1);
            row_acc_x(xbase + 3 * XROW, xsegoff, wx, q3);
#pragma unroll
            for (int c = 0; c < 4; c++) {
                float sendA = low0 ? q2[c] : q0[c];
                float recvA = __shfl_xor_sync(0xffffffffu, sendA, 4);
                xa[c] = (low0 ? q0[c] : q2[c]) + recvA;
                float sendB = low0 ? q3[c] : q1[c];
                float recvB = __shfl_xor_sync(0xffffffffu, sendB, 4);
                xb[c] = (low0 ? q1[c] : q3[c]) + recvB;
            }
        }

        // ---- loader publishes x_{t+2} into xs[t&1] (read next interval)
        if (loader) *(float4*)&xs[t & 1][xr][px4] = xn;

        __syncthreads();
        p = q;
    }

    // ---- final projection: out[b0r+m][j] = b_ph[j] + sum_k h[m][k]*W_ph[j][k]
    if (tid < ROWS * ODIM) {
        const int m = tid / ODIM;
        const int j = tid % ODIM;
        float s = b_ph[j];
#pragma unroll 4
        for (int k = 0; k < HDIM; k++)
            s += hb[p][m][physh(k)] * W_ph[j * HDIM + k];
        out[(size_t)(b0r + m) * ODIM + j] = s;
    }
}

extern "C" void kernel_launch(void* const* d_in, const int* in_sizes, int n_in,
                              void* d_out, int out_size) {
    const float* x    = (const float*)d_in[0];
    const float* W_hx = (const float*)d_in[1];
    const float* W_hh = (const float*)d_in[2];
    const float* b_hh = (const float*)d_in[3];
    const float* W_ph = (const float*)d_in[4];
    const float* b_ph = (const float*)d_in[5];
    float* out = (float*)d_out;

    rnn_fused_kernel<<<GRID, NTHREADS>>>(x, W_hx, W_hh, b_hh, W_ph, b_ph, out);
}

// round 10
// speedup vs baseline: 2.1187x; 2.1187x over previous
#include <cuda_runtime.h>

// VanillaRNN fused persistent kernel, v8 = v5 topology + select-free butterfly
// + HW tanh + anti-phase stagger.
// B=1024, T=512, I=64, H=128, O=10.
// Grid: 256 CTAs x 4 rows, 256 threads, 2 CTAs/SM (__launch_bounds__(256,2)).
//
// Thread mapping: g = warp*4 + (lane&3): column group; seg = lane>>2 in [0,8):
// 24-wide k-segment of the 192-wide concat(x_t, h_t).
// SELECT-FREE butterfly: each thread accumulates rows in the per-thread order
//   keepA = sb1+2*sb0, sendA = sb1+2*(1-sb0),
//   keepB = (1-sb1)+2*sb0, sendB = (1-sb1)+2*(1-sb0)
// and loads its 4 weight columns in sb2-permuted order
//   cg = {2*sb2, 2*sb2+1, 2*(1-sb2), 2*(1-sb2)+1}
// so every reduction stage is exactly  keep + shfl_xor(send)  with no FSELs.
//   stage0 (xor4):  ra = aKA + shfl(aSA); rb = aKB + shfl(aSB)
//   stage1 (xor8):  rc = ra + shfl(rb)
//   stage2 (xor16): f0 = rc[0]+shfl(rc[2]); f1 = rc[1]+shfl(rc[3])
// Lane finalizes row mstar = 2*sb0+sb1, cols {g+32*cg[0], g+32*cg[1]}.
// tanh via MUFU tanh.approx.f32. CTAs with bid>=148 run a ~640-cyc dummy
// chain once before the loop to anti-phase the two resident CTAs per SM.
// Segment stride 28 floats: 8 bases tile all 32 banks -> conflict-free LDS.128.

#define ROWS 4
#define NTHREADS 256
#define HDIM 128
#define IDIM 64
#define TSTEPS 512
#define ODIM 10
#define SEGF 24
#define SEGP 28
#define RSTRIDE 228
#define GRID 256

__device__ __forceinline__ unsigned long long ffma2(unsigned long long a,
                                                    unsigned long long b,
                                                    unsigned long long c) {
    unsigned long long d;
    asm("fma.rn.f32x2 %0, %1, %2, %3;" : "=l"(d) : "l"(a), "l"(b), "l"(c));
    return d;
}

__device__ __forceinline__ unsigned long long packf2(float lo, float hi) {
    return ((unsigned long long)__float_as_uint(hi) << 32) |
           (unsigned long long)__float_as_uint(lo);
}

__device__ __forceinline__ float sum2(unsigned long long a) {
    return __uint_as_float((unsigned)a) + __uint_as_float((unsigned)(a >> 32));
}

__device__ __forceinline__ float tanh_fast(float z) {
    float r;
    asm("tanh.approx.f32 %0, %1;" : "=f"(r) : "f"(z));
    return r;
}

__device__ __forceinline__ int physk(int k) { return k + 4 * (k / SEGF); }

__device__ __forceinline__ float wpick(const float* __restrict__ W_hx,
                                       const float* __restrict__ W_hh,
                                       int o, int k) {
    return (k < IDIM) ? W_hx[o * IDIM + k] : W_hh[o * HDIM + (k - IDIM)];
}

// accumulate one row's 24-k segment for this thread's 4 (permuted) cols
__device__ __forceinline__ void row_acc(const float* __restrict__ rowseg,
                                        const unsigned long long w[4][12],
                                        float sv[4]) {
    const ulonglong2* pp = (const ulonglong2*)rowseg;
    unsigned long long a0 = 0ull, a1 = 0ull, a2 = 0ull, a3 = 0ull;
#pragma unroll
    for (int i = 0; i < 6; i++) {
        ulonglong2 v = pp[i];
        a0 = ffma2(v.x, w[0][2 * i], a0);
        a1 = ffma2(v.x, w[1][2 * i], a1);
        a2 = ffma2(v.x, w[2][2 * i], a2);
        a3 = ffma2(v.x, w[3][2 * i], a3);
        a0 = ffma2(v.y, w[0][2 * i + 1], a0);
        a1 = ffma2(v.y, w[1][2 * i + 1], a1);
        a2 = ffma2(v.y, w[2][2 * i + 1], a2);
        a3 = ffma2(v.y, w[3][2 * i + 1], a3);
    }
    sv[0] = sum2(a0); sv[1] = sum2(a1); sv[2] = sum2(a2); sv[3] = sum2(a3);
}

__global__ void __launch_bounds__(NTHREADS, 2)
rnn_fused_kernel(const float* __restrict__ x,
                 const float* __restrict__ W_hx,
                 const float* __restrict__ W_hh,
                 const float* __restrict__ b_hh,
                 const float* __restrict__ W_ph,
                 const float* __restrict__ b_ph,
                 float* __restrict__ out) {
    __shared__ __align__(16) float buf[2][ROWS][RSTRIDE];

    const int tid  = threadIdx.x;
    const int lane = tid & 31;
    const int warp = tid >> 5;
    const int g    = warp * 4 + (lane & 3);   // col group 0..31
    const int seg  = lane >> 2;               // k-segment 0..7
    const int kb   = seg * SEGF;
    const int b0r  = blockIdx.x * ROWS;

    const int sb0 = seg & 1, sb1 = (seg >> 1) & 1, sb2 = (seg >> 2) & 1;

    // per-thread permuted column order (stage-2 select elimination)
    int cg[4];
    cg[0] = 2 * sb2; cg[1] = 2 * sb2 + 1;
    cg[2] = 2 * (1 - sb2); cg[3] = 2 * (1 - sb2) + 1;

    // ---- weights in permuted col order: 4 x 12 packed f32x2 (96 regs)
    unsigned long long w[4][12];
#pragma unroll
    for (int c = 0; c < 4; c++) {
        const int o = g + 32 * cg[c];
#pragma unroll
        for (int j = 0; j < 12; j++) {
            const int k0 = kb + 2 * j;
            w[c][j] = packf2(wpick(W_hx, W_hh, o, k0),
                             wpick(W_hx, W_hh, o, k0 + 1));
        }
    }

    // per-thread row order (stage-0/1 select elimination)
    const int rKA = sb1 + 2 * sb0;
    const int rSA = sb1 + 2 * (1 - sb0);
    const int rKB = (1 - sb1) + 2 * sb0;
    const int rSB = (1 - sb1) + 2 * (1 - sb0);
    const int segoff = seg * SEGP;
    const int oKA = rKA * RSTRIDE + segoff;
    const int oSA = rSA * RSTRIDE + segoff;
    const int oKB = rKB * RSTRIDE + segoff;
    const int oSB = rSB * RSTRIDE + segoff;

    const int mstar = 2 * sb0 + sb1;          // row this lane finalizes
    const int of0 = g + 32 * cg[0];
    const int of1 = g + 32 * cg[1];
    const float bb0 = b_hh[of0];
    const float bb1 = b_hh[of1];
    const int ph0 = physk(IDIM + of0);
    const int ph1 = physk(IDIM + of1);

    // ---- zero both buffers (h0 = 0)
    for (int i = tid; i < 2 * ROWS * RSTRIDE; i += NTHREADS)
        ((float*)buf)[i] = 0.0f;

    // ---- x loader: tid<64, row xr, float4 chunk c4 (24%4==0 -> no straddle)
    const int xr  = (tid >> 4) & 3;
    const int c4  = (tid & 15) * 4;
    const int pc4 = c4 + 4 * (c4 / SEGF);
    const bool loader = (tid < 64);
    const float* xrow = x + (size_t)(b0r + xr) * TSTEPS * IDIM;

    if (loader)
        *(float4*)&buf[0][xr][pc4] = *(const float4*)(xrow + c4);

    // ---- anti-phase stagger: second-wave CTAs burn ~640 cyc once so the two
    // resident CTAs' serial (tree/tanh/barrier) segments interleave with the
    // partner's FFMA block instead of coinciding. Harmless if pairing differs.
    if (blockIdx.x >= 148) {
        float d = (float)(tid + 1);
#pragma unroll 8
        for (int i = 0; i < 160; i++) d = fmaf(d, 0.99990f, 1.0f);
        if (d == 12345.678f) buf[0][0][SEGF] = d;   // never true; defeats DCE
    }
    __syncthreads();

    int p = 0;
    for (int t = 0; t < TSTEPS; t++) {
        float4 xn;
        if (loader) {
            const int tn = (t + 1 < TSTEPS) ? t + 1 : TSTEPS - 1;
            xn = *(const float4*)(xrow + (size_t)tn * IDIM + c4);
        }

        const float* base0 = &buf[p][0][0];

        // ---- pair A (stage-1 survivor): keep + shfl(send), no selects
        float ra[4];
        {
            float aK[4], aS[4];
            row_acc(base0 + oKA, w, aK);
            row_acc(base0 + oSA, w, aS);
#pragma unroll
            for (int c = 0; c < 4; c++)
                ra[c] = aK[c] + __shfl_xor_sync(0xffffffffu, aS[c], 4);
        }
        // ---- pair B
        float rb[4];
        {
            float aK[4], aS[4];
            row_acc(base0 + oKB, w, aK);
            row_acc(base0 + oSB, w, aS);
#pragma unroll
            for (int c = 0; c < 4; c++)
                rb[c] = aK[c] + __shfl_xor_sync(0xffffffffu, aS[c], 4);
        }

        // ---- stage 1 (xor 8): rows 2 -> 1
        float rc[4];
#pragma unroll
        for (int c = 0; c < 4; c++)
            rc[c] = ra[c] + __shfl_xor_sync(0xffffffffu, rb[c], 8);

        // ---- stage 2 (xor 16): cols 4 -> 2 (order pre-permuted via cg)
        const float f0 = rc[0] + __shfl_xor_sync(0xffffffffu, rc[2], 16);
        const float f1 = rc[1] + __shfl_xor_sync(0xffffffffu, rc[3], 16);

        // ---- publish h_t: row mstar, cols of0, of1
        const int q = p ^ 1;
        buf[q][mstar][ph0] = tanh_fast(f0 + bb0);
        buf[q][mstar][ph1] = tanh_fast(f1 + bb1);

        if (loader) *(float4*)&buf[q][xr][pc4] = xn;

        __syncthreads();
        p = q;
    }

    // ---- final projection: out[b0r+m][j] = b_ph[j] + sum_k h[m][k]*W_ph[j][k]
    if (tid < ROWS * ODIM) {
        const int m = tid / ODIM;
        const int j = tid % ODIM;
        float s = b_ph[j];
#pragma unroll 4
        for (int k = 0; k < HDIM; k++)
            s += buf[p][m][physk(IDIM + k)] * W_ph[j * HDIM + k];
        out[(size_t)(b0r + m) * ODIM + j] = s;
    }
}

extern "C" void kernel_launch(void* const* d_in, const int* in_sizes, int n_in,
                              void* d_out, int out_size) {
    const float* x    = (const float*)d_in[0];
    const float* W_hx = (const float*)d_in[1];
    const float* W_hh = (const float*)d_in[2];
    const float* b_hh = (const float*)d_in[3];
    const float* W_ph = (const float*)d_in[4];
    const float* b_ph = (const float*)d_in[5];
    float* out = (float*)d_out;

    rnn_fused_kernel<<<GRID, NTHREADS>>>(x, W_hx, W_hh, b_hh, W_ph, b_ph, out);
}